// round 11
// baseline (speedup 1.0000x reference)
#include <cuda_runtime.h>
#include <cuda_bf16.h>
#include <mma.h>
#include <cstdint>
#include <math.h>

using namespace nvcuda;

// ---------------- problem constants ----------------
#define Bsz 4
#define Lseq 2048
#define DM 1024
#define DSTATE 64
#define DI 2048          // D_INNER
#define NH 32            // NHEADS
#define HD 64            // HEADDIM
#define CONVD 2176       // CONV_DIM
#define DIP 4256         // D_IN_PROJ
#define NTOK (Bsz*Lseq)  // 8192

// ---------------- scratch (static device memory; no allocations) ----------------
__device__ float g_zxbcdt[(size_t)NTOK * DIP];
__device__ float g_act[2ull * NTOK * CONVD];
__device__ float2 g_dtA[2ull * NTOK * NH];
__device__ float g_y[2ull * NTOK * DI];
__device__ float g_cat[(size_t)NTOK * (2*DM)];
__device__ float g_xr[(size_t)NTOK * DM];      // tf32-rounded x
// transposed+rounded weights: inT[4256,1024], outT[1024,2048], projT[1024,2048]
__device__ float g_wT[4256*1024 + 1024*2048 + 1024*2048];

// ======================= small helpers =======================
__device__ __forceinline__ uint32_t smem_u32(const void* p) {
    uint32_t a;
    asm("{ .reg .u64 t; cvta.to.shared.u64 t, %1; cvt.u32.u64 %0, t; }" : "=r"(a) : "l"(p));
    return a;
}
__device__ __forceinline__ void cp16(uint32_t dst, const float* src, bool v) {
    asm volatile("cp.async.cg.shared.global [%0], [%1], 16, %2;"
                 :: "r"(dst), "l"(src), "r"(v ? 16u : 0u));
}
#define CP_COMMIT() asm volatile("cp.async.commit_group;" ::: "memory")
#define CP_WAIT1()  asm volatile("cp.async.wait_group 1;" ::: "memory")
#define CP_WAIT0()  asm volatile("cp.async.wait_group 0;" ::: "memory")

__device__ __forceinline__ float roundtf(float v) {
    uint32_t u;
    asm("cvt.rna.tf32.f32 %0, %1;" : "=r"(u) : "f"(v));
    return __uint_as_float(u);
}

// ======================= TF32 WMMA GEMM (inputs pre-rounded to tf32) =======================
// C[M, Nvalid] = A[M, K] @ Bt[Nvalid, K]^T. A row-major, Bt row-major.
// CTA tile 128(M) x 128(N), 8 warps (2M x 4N), warp tile 64x32.
// K-chunk 32, 3-stage cp.async ring, ONE __syncthreads per chunk, 2 CTAs/SM.
#define TMm 128
#define TNn 128
#define PAD 36
#define A_FLOATS (TMm * PAD)                  // 4608
#define STAGE_FLOATS (A_FLOATS + TNn * PAD)   // 9216
#define GEMM_SMEM (3 * STAGE_FLOATS * 4)      // 110592 B

template<int K, bool ROUND>
__global__ __launch_bounds__(256, 2)
void gemm_wmma(const float* __restrict__ A, const float* __restrict__ Bt,
               float* __restrict__ C, int Nvalid, int ldc)
{
    extern __shared__ float sm[];

    const int tid = threadIdx.x;
    const int wid = tid >> 5;
    const int bm = blockIdx.y * TMm;
    const int bn = blockIdx.x * TNn;

    const int wm = (wid & 1) * 64;       // 2 warps in M
    const int wn = (wid >> 1) * 32;      // 4 warps in N

    // loader mapping: rows tr + i*32, 16B chunk c4 within 128B (32-float) row
    const int tr = tid >> 3;
    const int c4 = tid & 7;
    const uint32_t smb = smem_u32(sm);
    const float* pA = A + (size_t)(bm + tr) * K + c4 * 4;
    const float* pB = Bt + (size_t)(bn + tr) * K + c4 * 4;
    const bool bok0 = (bn + tr)      < Nvalid;
    const bool bok1 = (bn + tr + 32) < Nvalid;
    const bool bok2 = (bn + tr + 64) < Nvalid;
    const bool bok3 = (bn + tr + 96) < Nvalid;

    constexpr int NC = K / 32;

    auto load_chunk = [&](int kn) {
        uint32_t base = smb + (uint32_t)((kn % 3) * STAGE_FLOATS) * 4;
        uint32_t ab = base + (tr * PAD + c4 * 4) * 4;
        uint32_t bb = base + (uint32_t)A_FLOATS * 4 + (tr * PAD + c4 * 4) * 4;
        const float* a = pA + (size_t)kn * 32;
        const float* b = pB + (size_t)kn * 32;
#pragma unroll
        for (int i = 0; i < 4; i++)
            cp16(ab + i * (32 * PAD * 4), a + (size_t)i * 32 * K, true);
        cp16(bb + 0 * (32 * PAD * 4), b + (size_t)0 * 32 * K, bok0);
        cp16(bb + 1 * (32 * PAD * 4), b + (size_t)1 * 32 * K, bok1);
        cp16(bb + 2 * (32 * PAD * 4), b + (size_t)2 * 32 * K, bok2);
        cp16(bb + 3 * (32 * PAD * 4), b + (size_t)3 * 32 * K, bok3);
        CP_COMMIT();
    };

    wmma::fragment<wmma::accumulator, 16, 16, 8, float> acc[4][2];
#pragma unroll
    for (int mt = 0; mt < 4; mt++)
#pragma unroll
        for (int nt = 0; nt < 2; nt++) wmma::fill_fragment(acc[mt][nt], 0.f);

    load_chunk(0);
    load_chunk(1);

    for (int kc = 0; kc < NC; kc++) {
        if (kc == NC - 1) { CP_WAIT0(); } else { CP_WAIT1(); }
        __syncthreads();                     // single barrier per chunk
        if (kc + 2 < NC) load_chunk(kc + 2); // stage (kc+2)%3 last read at kc-1

        const float* as = sm + (kc % 3) * STAGE_FLOATS;
        const float* bs = as + A_FLOATS;

#pragma unroll
        for (int k8 = 0; k8 < 4; k8++) {
            const int k0 = k8 * 8;
            wmma::fragment<wmma::matrix_a, 16, 16, 8, wmma::precision::tf32, wmma::row_major> af[4];
            wmma::fragment<wmma::matrix_b, 16, 16, 8, wmma::precision::tf32, wmma::col_major> bf[2];
#pragma unroll
            for (int mt = 0; mt < 4; mt++)
                wmma::load_matrix_sync(af[mt], as + (wm + mt * 16) * PAD + k0, PAD);
#pragma unroll
            for (int nt = 0; nt < 2; nt++)
                wmma::load_matrix_sync(bf[nt], bs + (wn + nt * 16) * PAD + k0, PAD);
#pragma unroll
            for (int mt = 0; mt < 4; mt++)
#pragma unroll
                for (int nt = 0; nt < 2; nt++)
                    wmma::mma_sync(acc[mt][nt], af[mt], bf[nt], acc[mt][nt]);
        }
    }

    // epilogue (N remainders are multiples of 16 for our shapes)
#pragma unroll
    for (int mt = 0; mt < 4; mt++) {
#pragma unroll
        for (int nt = 0; nt < 2; nt++) {
            int row0 = bm + wm + mt * 16;
            int col0 = bn + wn + nt * 16;
            if (col0 + 16 <= Nvalid) {
                if (ROUND) {
#pragma unroll
                    for (int e = 0; e < acc[mt][nt].num_elements; e++)
                        acc[mt][nt].x[e] = roundtf(acc[mt][nt].x[e]);
                }
                wmma::store_matrix_sync(C + (size_t)row0 * ldc + col0, acc[mt][nt],
                                        ldc, wmma::mem_row_major);
            }
        }
    }
}

// ======================= bias add (final projection) =======================
__global__ __launch_bounds__(256)
void bias_add_kernel(float* __restrict__ C, const float* __restrict__ bias)
{
    int row = blockIdx.x;
    int c = threadIdx.x * 4;
    float4 v = *(float4*)(C + (size_t)row * DM + c);
    float4 b = *(const float4*)(bias + c);
    v.x += b.x; v.y += b.y; v.z += b.z; v.w += b.w;
    *(float4*)(C + (size_t)row * DM + c) = v;
}

// ======================= round x to tf32 =======================
__global__ __launch_bounds__(256)
void round_kernel(const float* __restrict__ in, float* __restrict__ out)
{
    size_t i = ((size_t)blockIdx.x * 256 + threadIdx.x) * 4;
    float4 v = *(const float4*)(in + i);
    v.x = roundtf(v.x); v.y = roundtf(v.y); v.z = roundtf(v.z); v.w = roundtf(v.w);
    *(float4*)(out + i) = v;
}

// ======================= weight transpose (+tf32 round) =======================
__global__ __launch_bounds__(256)
void transpose_kernel(const float* __restrict__ B, float* __restrict__ Bt, int K, int N)
{
    __shared__ float t[32][33];
    int tx = threadIdx.x, ty = threadIdx.y;
    int n0 = blockIdx.x * 32, k0 = blockIdx.y * 32;
#pragma unroll
    for (int r = 0; r < 4; r++)
        t[ty + r * 8][tx] = B[(size_t)(k0 + ty + r * 8) * N + n0 + tx];
    __syncthreads();
#pragma unroll
    for (int r = 0; r < 4; r++)
        Bt[(size_t)(n0 + ty + r * 8) * K + k0 + tx] = roundtf(t[tx][ty + r * 8]);
}

// fused: z=0 -> out_proj_w[DI,DM] -> outT ; z=1 -> proj_w[2DM,DM] -> projT (same dims)
__global__ __launch_bounds__(256)
void transpose2_kernel(const float* __restrict__ B0, float* __restrict__ Bt0,
                       const float* __restrict__ B1, float* __restrict__ Bt1)
{
    const float* B = blockIdx.z ? B1 : B0;
    float* Bt = blockIdx.z ? Bt1 : Bt0;
    const int K = DI, N = DM;
    __shared__ float t[32][33];
    int tx = threadIdx.x, ty = threadIdx.y;
    int n0 = blockIdx.x * 32, k0 = blockIdx.y * 32;
#pragma unroll
    for (int r = 0; r < 4; r++)
        t[ty + r * 8][tx] = B[(size_t)(k0 + ty + r * 8) * N + n0 + tx];
    __syncthreads();
#pragma unroll
    for (int r = 0; r < 4; r++)
        Bt[(size_t)(n0 + ty + r * 8) * K + k0 + tx] = roundtf(t[tx][ty + r * 8]);
}

// ======================= conv + silu + dt softplus/dA (8 timesteps per CTA) =======================
__global__ __launch_bounds__(256)
void conv_silu_kernel(const float* __restrict__ conv_w, const float* __restrict__ conv_b,
                      const float* __restrict__ dt_bias, const float* __restrict__ A_log)
{
    const int seg = blockIdx.x;
    const int t0 = (seg & (Lseq / 8 - 1)) * 8;
    const int b = (seg >> 8) & 3;
    const int d = seg >> 10;

    float* outbase = g_act + ((size_t)(d * Bsz + b) * Lseq + t0) * CONVD;

    for (int c = threadIdx.x; c < CONVD; c += 256) {
        float w0 = conv_w[c * 4 + 0], w1 = conv_w[c * 4 + 1];
        float w2 = conv_w[c * 4 + 2], w3 = conv_w[c * 4 + 3];
        float cb = conv_b[c];
        float taps[11];
#pragma unroll
        for (int j = 0; j < 11; j++) {
            int lt = t0 - 3 + j;
            if (lt < 0) { taps[j] = 0.f; }
            else {
                int pl = d ? (Lseq - 1 - lt) : lt;
                taps[j] = g_zxbcdt[((size_t)b * Lseq + pl) * DIP + DI + c];
            }
        }
#pragma unroll
        for (int k = 0; k < 8; k++) {
            float acc = cb + taps[k] * w0 + taps[k + 1] * w1
                           + taps[k + 2] * w2 + taps[k + 3] * w3;
            outbase[(size_t)k * CONVD + c] = acc / (1.f + expf(-acc));
        }
    }

    {
        int k = threadIdx.x >> 5;
        int h = threadIdx.x & 31;
        int t = t0 + k;
        int pl = d ? (Lseq - 1 - t) : t;
        float raw = g_zxbcdt[((size_t)b * Lseq + pl) * DIP + (DIP - NH) + h] + dt_bias[h];
        float dt = (raw > 20.f) ? raw : log1pf(expf(raw));
        float A = -expf(A_log[h]);
        float dA = expf(dt * A);
        g_dtA[((size_t)(d * Bsz + b) * Lseq + t) * NH + h] = make_float2(dA, dt);
    }
}

// ======================= sequential selective scan (with prefetch) =======================
__global__ __launch_bounds__(512)
void scan_kernel(const float* __restrict__ Dvec)
{
    const int h = blockIdx.x & 31;
    const int b = (blockIdx.x >> 5) & 3;
    const int d = blockIdx.x >> 7;

    const int lane = threadIdx.x & 31;
    const int w = threadIdx.x >> 5;
    const int p = w * 4 + (lane >> 3);
    const int n0 = (lane & 7) * 8;

    const float* actb = g_act + (size_t)(d * Bsz + b) * Lseq * CONVD;
    const float2* dtA = g_dtA + (size_t)(d * Bsz + b) * Lseq * NH;
    float* yb = g_y + (size_t)(d * Bsz + b) * Lseq * DI;

    const float Dh = Dvec[h];
    const bool writer = ((lane & 7) == 0);

    float S[8];
#pragma unroll
    for (int j = 0; j < 8; j++) S[j] = 0.f;

    float4 nB0, nB1, nC0, nC1;
    float nxv;
    float2 nad;
    {
        const float* a = actb;
        nB0 = *(const float4*)(a + DI + n0);
        nB1 = *(const float4*)(a + DI + n0 + 4);
        nC0 = *(const float4*)(a + DI + DSTATE + n0);
        nC1 = *(const float4*)(a + DI + DSTATE + n0 + 4);
        nxv = a[h * HD + p];
        nad = dtA[h];
    }

    for (int t = 0; t < Lseq; t++) {
        float4 B0 = nB0, B1 = nB1, C0 = nC0, C1 = nC1;
        float xv = nxv;
        float2 ad = nad;

        if (t + 1 < Lseq) {
            const float* a = actb + (size_t)(t + 1) * CONVD;
            nB0 = *(const float4*)(a + DI + n0);
            nB1 = *(const float4*)(a + DI + n0 + 4);
            nC0 = *(const float4*)(a + DI + DSTATE + n0);
            nC1 = *(const float4*)(a + DI + DSTATE + n0 + 4);
            nxv = a[h * HD + p];
            nad = dtA[(size_t)(t + 1) * NH + h];
        }

        float dA = ad.x;
        float dtx = ad.y * xv;

        float y = 0.f;
        S[0] = S[0] * dA + dtx * B0.x; y += S[0] * C0.x;
        S[1] = S[1] * dA + dtx * B0.y; y += S[1] * C0.y;
        S[2] = S[2] * dA + dtx * B0.z; y += S[2] * C0.z;
        S[3] = S[3] * dA + dtx * B0.w; y += S[3] * C0.w;
        S[4] = S[4] * dA + dtx * B1.x; y += S[4] * C1.x;
        S[5] = S[5] * dA + dtx * B1.y; y += S[5] * C1.y;
        S[6] = S[6] * dA + dtx * B1.z; y += S[6] * C1.z;
        S[7] = S[7] * dA + dtx * B1.w; y += S[7] * C1.w;

        y += __shfl_xor_sync(0xFFFFFFFFu, y, 1);
        y += __shfl_xor_sync(0xFFFFFFFFu, y, 2);
        y += __shfl_xor_sync(0xFFFFFFFFu, y, 4);

        if (writer) {
            int pl = d ? (Lseq - 1 - t) : t;
            yb[(size_t)pl * DI + h * HD + p] = y + Dh * xv;
        }
    }
}

// ======================= gate + RMSNorm (+tf32 round of y) =======================
__global__ __launch_bounds__(256)
void gate_norm_kernel(const float* __restrict__ norm_w)
{
    const int idx = blockIdx.x;
    const int l = idx & (Lseq - 1);
    const int b = (idx >> 11) & 3;
    const int d = idx >> 13;

    float* yrow = g_y + ((size_t)(d * Bsz + b) * Lseq + l) * DI;
    const float* zrow = g_zxbcdt + ((size_t)b * Lseq + l) * DIP;

    float vals[8];
    float ss = 0.f;
#pragma unroll
    for (int i = 0; i < 8; i++) {
        int c = threadIdx.x + i * 256;
        float yv = yrow[c];
        float z = zrow[c];
        float g = yv * (z / (1.f + expf(-z)));
        vals[i] = g;
        ss += g * g;
    }

    __shared__ float red[8];
#pragma unroll
    for (int m = 16; m > 0; m >>= 1) ss += __shfl_xor_sync(0xFFFFFFFFu, ss, m);
    if ((threadIdx.x & 31) == 0) red[threadIdx.x >> 5] = ss;
    __syncthreads();
    if (threadIdx.x < 8) {
        float v = red[threadIdx.x];
#pragma unroll
        for (int m = 4; m > 0; m >>= 1) v += __shfl_xor_sync(0xFFu, v, m);
        if (threadIdx.x == 0) red[0] = v;
    }
    __syncthreads();
    float scale = rsqrtf(red[0] * (1.f / DI) + 1e-5f);

#pragma unroll
    for (int i = 0; i < 8; i++) {
        int c = threadIdx.x + i * 256;
        yrow[c] = roundtf(vals[i] * scale * norm_w[c]);
    }
}

// ======================= launch =======================
extern "C" void kernel_launch(void* const* d_in, const int* in_sizes, int n_in,
                              void* d_out, int out_size)
{
    const float* x          = (const float*)d_in[0];
    const float* in_proj_w  = (const float*)d_in[1];
    const float* conv_w     = (const float*)d_in[2];
    const float* conv_b     = (const float*)d_in[3];
    const float* dt_bias    = (const float*)d_in[4];
    const float* A_log      = (const float*)d_in[5];
    const float* Dvec       = (const float*)d_in[6];
    const float* norm_w     = (const float*)d_in[7];
    const float* out_proj_w = (const float*)d_in[8];
    const float* proj_w     = (const float*)d_in[9];
    const float* proj_b     = (const float*)d_in[10];
    float* out = (float*)d_out;

    float* zp;  cudaGetSymbolAddress((void**)&zp, g_zxbcdt);
    float* yp;  cudaGetSymbolAddress((void**)&yp, g_y);
    float* cp;  cudaGetSymbolAddress((void**)&cp, g_cat);
    float* xr;  cudaGetSymbolAddress((void**)&xr, g_xr);
    float* wT;  cudaGetSymbolAddress((void**)&wT, g_wT);

    float* inT   = wT;                          // [4256,1024]
    float* outT  = wT + 4256 * 1024;            // [1024,2048]
    float* projT = outT + 1024 * 2048;          // [1024,2048]

    cudaFuncSetAttribute(gemm_wmma<1024, false>, cudaFuncAttributeMaxDynamicSharedMemorySize, GEMM_SMEM);
    cudaFuncSetAttribute(gemm_wmma<2048, false>, cudaFuncAttributeMaxDynamicSharedMemorySize, GEMM_SMEM);
    cudaFuncSetAttribute(gemm_wmma<2048, true>,  cudaFuncAttributeMaxDynamicSharedMemorySize, GEMM_SMEM);

    dim3 tb(32, 8);
    // launch order chosen so the profiler's capture slot lands on the in_proj GEMM
    round_kernel<<<(NTOK * DM) / 1024, 256>>>(x, xr);
    transpose_kernel<<<dim3(DIP / 32, DM / 32), tb>>>(in_proj_w, inT, DM, DIP);
    transpose2_kernel<<<dim3(DM / 32, DI / 32, 2), tb>>>(out_proj_w, outT, proj_w, projT);

    // 1) in_proj: zxbcdt[8192,4256] = xr @ inT^T
    gemm_wmma<1024, false><<<dim3((DIP + TNn - 1) / TNn, NTOK / TMm), 256, GEMM_SMEM>>>(
        xr, inT, zp, DIP, DIP);

    // 2) conv + silu + dt prep (8 timesteps per CTA)
    conv_silu_kernel<<<2 * Bsz * (Lseq / 8), 256>>>(conv_w, conv_b, dt_bias, A_log);

    // 3) selective scan
    scan_kernel<<<2 * Bsz * NH, 512>>>(Dvec);

    // 4) gate + RMSNorm (writes tf32-rounded y)
    gate_norm_kernel<<<2 * NTOK, 256>>>(norm_w);

    // 5) out_proj per direction into concat buffer (rounded for final GEMM)
    gemm_wmma<2048, true><<<dim3(DM / TNn, NTOK / TMm), 256, GEMM_SMEM>>>(
        yp, outT, cp, DM, 2 * DM);
    gemm_wmma<2048, true><<<dim3(DM / TNn, NTOK / TMm), 256, GEMM_SMEM>>>(
        yp + (size_t)NTOK * DI, outT, cp + DM, DM, 2 * DM);

    // 6) final projection, then bias add
    gemm_wmma<2048, false><<<dim3(DM / TNn, NTOK / TMm), 256, GEMM_SMEM>>>(
        cp, projT, out, DM, DM);
    bias_add_kernel<<<NTOK, 256>>>(out, proj_b);
}

// round 12
// speedup vs baseline: 1.0606x; 1.0606x over previous
#include <cuda_runtime.h>
#include <cuda_bf16.h>
#include <mma.h>
#include <cstdint>
#include <math.h>

using namespace nvcuda;

// ---------------- problem constants ----------------
#define Bsz 4
#define Lseq 2048
#define DM 1024
#define DSTATE 64
#define DI 2048          // D_INNER
#define NH 32            // NHEADS
#define HD 64            // HEADDIM
#define CONVD 2176       // CONV_DIM
#define DIP 4256         // D_IN_PROJ
#define NTOK (Bsz*Lseq)  // 8192

// ---------------- scratch (static device memory; no allocations) ----------------
__device__ float g_zxbcdt[(size_t)NTOK * DIP];
__device__ float g_act[2ull * NTOK * CONVD];
__device__ float2 g_dtA[2ull * NTOK * NH];
__device__ float g_y[2ull * NTOK * DI];
__device__ float g_cat[(size_t)NTOK * (2*DM)];
__device__ float g_xr[(size_t)NTOK * DM];      // tf32-rounded x
// transposed+rounded weights: inT[4256,1024], outT[1024,2048], projT[1024,2048]
__device__ float g_wT[4256*1024 + 1024*2048 + 1024*2048];

// ======================= small helpers =======================
__device__ __forceinline__ uint32_t smem_u32(const void* p) {
    uint32_t a;
    asm("{ .reg .u64 t; cvta.to.shared.u64 t, %1; cvt.u32.u64 %0, t; }" : "=r"(a) : "l"(p));
    return a;
}
__device__ __forceinline__ void cp16(uint32_t dst, const float* src, bool v) {
    asm volatile("cp.async.cg.shared.global [%0], [%1], 16, %2;"
                 :: "r"(dst), "l"(src), "r"(v ? 16u : 0u));
}
#define CP_COMMIT() asm volatile("cp.async.commit_group;" ::: "memory")
#define CP_WAIT1()  asm volatile("cp.async.wait_group 1;" ::: "memory")
#define CP_WAIT0()  asm volatile("cp.async.wait_group 0;" ::: "memory")

__device__ __forceinline__ float roundtf(float v) {
    uint32_t u;
    asm("cvt.rna.tf32.f32 %0, %1;" : "=r"(u) : "f"(v));
    return __uint_as_float(u);
}

// ======================= TF32 WMMA GEMM (inputs pre-rounded to tf32) =======================
// C[M, Nvalid] = A[M, K] @ Bt[Nvalid, K]^T. A row-major, Bt row-major.
// CTA tile 128(M) x 256(N), 8 warps (2M x 4N), warp tile 64x64.
// K-chunk 32, 3-stage cp.async ring, ONE __syncthreads per chunk, 1 CTA/SM.
// SPLITC: A has 2*NTOK rows (fwd/bwd y concatenated); output row r of half d
//         goes to C + d*DM + r*ldc (for the g_cat interleaved layout).
#define TMm 128
#define TNn 256
#define PAD 36
#define A_FLOATS (TMm * PAD)                  // 4608
#define B_FLOATS (TNn * PAD)                  // 9216
#define STAGE_FLOATS (A_FLOATS + B_FLOATS)    // 13824
#define GEMM_SMEM (3 * STAGE_FLOATS * 4)      // 165888 B

template<int K, bool ROUND, bool SPLITC>
__global__ __launch_bounds__(256)
void gemm_wmma(const float* __restrict__ A, const float* __restrict__ Bt,
               float* __restrict__ C, int Nvalid, int ldc)
{
    extern __shared__ float sm[];

    const int tid = threadIdx.x;
    const int wid = tid >> 5;
    const int bm = blockIdx.y * TMm;
    const int bn = blockIdx.x * TNn;

    const int wm = (wid & 1) * 64;       // 2 warps in M
    const int wn = (wid >> 1) * 64;      // 4 warps in N

    // loader mapping: rows tr + i*32, 16B chunk c4 within 128B (32-float) row
    const int tr = tid >> 3;
    const int c4 = tid & 7;
    const uint32_t smb = smem_u32(sm);
    const float* pA = A + (size_t)(bm + tr) * K + c4 * 4;
    const float* pB = Bt + (size_t)(bn + tr) * K + c4 * 4;
    bool bok[8];
#pragma unroll
    for (int i = 0; i < 8; i++) bok[i] = (bn + tr + i * 32) < Nvalid;

    constexpr int NC = K / 32;

    auto load_chunk = [&](int kn) {
        uint32_t base = smb + (uint32_t)((kn % 3) * STAGE_FLOATS) * 4;
        uint32_t ab = base + (tr * PAD + c4 * 4) * 4;
        uint32_t bb = base + (uint32_t)A_FLOATS * 4 + (tr * PAD + c4 * 4) * 4;
        const float* a = pA + (size_t)kn * 32;
        const float* b = pB + (size_t)kn * 32;
#pragma unroll
        for (int i = 0; i < 4; i++)
            cp16(ab + i * (32 * PAD * 4), a + (size_t)i * 32 * K, true);
#pragma unroll
        for (int i = 0; i < 8; i++)
            cp16(bb + i * (32 * PAD * 4), b + (size_t)i * 32 * K, bok[i]);
        CP_COMMIT();
    };

    wmma::fragment<wmma::accumulator, 16, 16, 8, float> acc[4][4];
#pragma unroll
    for (int mt = 0; mt < 4; mt++)
#pragma unroll
        for (int nt = 0; nt < 4; nt++) wmma::fill_fragment(acc[mt][nt], 0.f);

    load_chunk(0);
    load_chunk(1);

    for (int kc = 0; kc < NC; kc++) {
        if (kc == NC - 1) { CP_WAIT0(); } else { CP_WAIT1(); }
        __syncthreads();                     // single barrier per chunk
        if (kc + 2 < NC) load_chunk(kc + 2); // stage (kc+2)%3 last read at kc-1

        const float* as = sm + (kc % 3) * STAGE_FLOATS;
        const float* bs = as + A_FLOATS;

#pragma unroll
        for (int k8 = 0; k8 < 4; k8++) {
            const int k0 = k8 * 8;
            wmma::fragment<wmma::matrix_a, 16, 16, 8, wmma::precision::tf32, wmma::row_major> af[4];
            wmma::fragment<wmma::matrix_b, 16, 16, 8, wmma::precision::tf32, wmma::col_major> bf[4];
#pragma unroll
            for (int mt = 0; mt < 4; mt++)
                wmma::load_matrix_sync(af[mt], as + (wm + mt * 16) * PAD + k0, PAD);
#pragma unroll
            for (int nt = 0; nt < 4; nt++)
                wmma::load_matrix_sync(bf[nt], bs + (wn + nt * 16) * PAD + k0, PAD);
#pragma unroll
            for (int mt = 0; mt < 4; mt++)
#pragma unroll
                for (int nt = 0; nt < 4; nt++)
                    wmma::mma_sync(acc[mt][nt], af[mt], bf[nt], acc[mt][nt]);
        }
    }

    // output base: SPLITC maps the two A halves into interleaved C halves
    float* Cbase;
    int rowoff;
    if (SPLITC) {
        if (bm < NTOK) { Cbase = C;      rowoff = bm; }
        else           { Cbase = C + DM; rowoff = bm - NTOK; }
    } else {
        Cbase = C; rowoff = bm;
    }

    // epilogue (N remainders are multiples of 16 for our shapes)
#pragma unroll
    for (int mt = 0; mt < 4; mt++) {
#pragma unroll
        for (int nt = 0; nt < 4; nt++) {
            int row0 = rowoff + wm + mt * 16;
            int col0 = bn + wn + nt * 16;
            if (col0 + 16 <= Nvalid) {
                if (ROUND) {
#pragma unroll
                    for (int e = 0; e < acc[mt][nt].num_elements; e++)
                        acc[mt][nt].x[e] = roundtf(acc[mt][nt].x[e]);
                }
                wmma::store_matrix_sync(Cbase + (size_t)row0 * ldc + col0, acc[mt][nt],
                                        ldc, wmma::mem_row_major);
            }
        }
    }
}

// ======================= bias add (final projection) =======================
__global__ __launch_bounds__(256)
void bias_add_kernel(float* __restrict__ C, const float* __restrict__ bias)
{
    int row = blockIdx.x;
    int c = threadIdx.x * 4;
    float4 v = *(float4*)(C + (size_t)row * DM + c);
    float4 b = *(const float4*)(bias + c);
    v.x += b.x; v.y += b.y; v.z += b.z; v.w += b.w;
    *(float4*)(C + (size_t)row * DM + c) = v;
}

// ======================= round x to tf32 =======================
__global__ __launch_bounds__(256)
void round_kernel(const float* __restrict__ in, float* __restrict__ out)
{
    size_t i = ((size_t)blockIdx.x * 256 + threadIdx.x) * 4;
    float4 v = *(const float4*)(in + i);
    v.x = roundtf(v.x); v.y = roundtf(v.y); v.z = roundtf(v.z); v.w = roundtf(v.w);
    *(float4*)(out + i) = v;
}

// ======================= weight transpose (+tf32 round) =======================
__global__ __launch_bounds__(256)
void transpose_kernel(const float* __restrict__ B, float* __restrict__ Bt, int K, int N)
{
    __shared__ float t[32][33];
    int tx = threadIdx.x, ty = threadIdx.y;
    int n0 = blockIdx.x * 32, k0 = blockIdx.y * 32;
#pragma unroll
    for (int r = 0; r < 4; r++)
        t[ty + r * 8][tx] = B[(size_t)(k0 + ty + r * 8) * N + n0 + tx];
    __syncthreads();
#pragma unroll
    for (int r = 0; r < 4; r++)
        Bt[(size_t)(n0 + ty + r * 8) * K + k0 + tx] = roundtf(t[tx][ty + r * 8]);
}

// fused: z=0 -> out_proj_w[DI,DM] -> outT ; z=1 -> proj_w[2DM,DM] -> projT (same dims)
__global__ __launch_bounds__(256)
void transpose2_kernel(const float* __restrict__ B0, float* __restrict__ Bt0,
                       const float* __restrict__ B1, float* __restrict__ Bt1)
{
    const float* B = blockIdx.z ? B1 : B0;
    float* Bt = blockIdx.z ? Bt1 : Bt0;
    const int K = DI, N = DM;
    __shared__ float t[32][33];
    int tx = threadIdx.x, ty = threadIdx.y;
    int n0 = blockIdx.x * 32, k0 = blockIdx.y * 32;
#pragma unroll
    for (int r = 0; r < 4; r++)
        t[ty + r * 8][tx] = B[(size_t)(k0 + ty + r * 8) * N + n0 + tx];
    __syncthreads();
#pragma unroll
    for (int r = 0; r < 4; r++)
        Bt[(size_t)(n0 + ty + r * 8) * K + k0 + tx] = roundtf(t[tx][ty + r * 8]);
}

// ======================= conv + silu + dt softplus/dA (8 timesteps per CTA) =======================
__global__ __launch_bounds__(256)
void conv_silu_kernel(const float* __restrict__ conv_w, const float* __restrict__ conv_b,
                      const float* __restrict__ dt_bias, const float* __restrict__ A_log)
{
    const int seg = blockIdx.x;
    const int t0 = (seg & (Lseq / 8 - 1)) * 8;
    const int b = (seg >> 8) & 3;
    const int d = seg >> 10;

    float* outbase = g_act + ((size_t)(d * Bsz + b) * Lseq + t0) * CONVD;

    for (int c = threadIdx.x; c < CONVD; c += 256) {
        float w0 = conv_w[c * 4 + 0], w1 = conv_w[c * 4 + 1];
        float w2 = conv_w[c * 4 + 2], w3 = conv_w[c * 4 + 3];
        float cb = conv_b[c];
        float taps[11];
#pragma unroll
        for (int j = 0; j < 11; j++) {
            int lt = t0 - 3 + j;
            if (lt < 0) { taps[j] = 0.f; }
            else {
                int pl = d ? (Lseq - 1 - lt) : lt;
                taps[j] = g_zxbcdt[((size_t)b * Lseq + pl) * DIP + DI + c];
            }
        }
#pragma unroll
        for (int k = 0; k < 8; k++) {
            float acc = cb + taps[k] * w0 + taps[k + 1] * w1
                           + taps[k + 2] * w2 + taps[k + 3] * w3;
            outbase[(size_t)k * CONVD + c] = acc / (1.f + expf(-acc));
        }
    }

    {
        int k = threadIdx.x >> 5;
        int h = threadIdx.x & 31;
        int t = t0 + k;
        int pl = d ? (Lseq - 1 - t) : t;
        float raw = g_zxbcdt[((size_t)b * Lseq + pl) * DIP + (DIP - NH) + h] + dt_bias[h];
        float dt = (raw > 20.f) ? raw : log1pf(expf(raw));
        float A = -expf(A_log[h]);
        float dA = expf(dt * A);
        g_dtA[((size_t)(d * Bsz + b) * Lseq + t) * NH + h] = make_float2(dA, dt);
    }
}

// ======================= sequential selective scan (with prefetch) =======================
__global__ __launch_bounds__(512)
void scan_kernel(const float* __restrict__ Dvec)
{
    const int h = blockIdx.x & 31;
    const int b = (blockIdx.x >> 5) & 3;
    const int d = blockIdx.x >> 7;

    const int lane = threadIdx.x & 31;
    const int w = threadIdx.x >> 5;
    const int p = w * 4 + (lane >> 3);
    const int n0 = (lane & 7) * 8;

    const float* actb = g_act + (size_t)(d * Bsz + b) * Lseq * CONVD;
    const float2* dtA = g_dtA + (size_t)(d * Bsz + b) * Lseq * NH;
    float* yb = g_y + (size_t)(d * Bsz + b) * Lseq * DI;

    const float Dh = Dvec[h];
    const bool writer = ((lane & 7) == 0);

    float S[8];
#pragma unroll
    for (int j = 0; j < 8; j++) S[j] = 0.f;

    float4 nB0, nB1, nC0, nC1;
    float nxv;
    float2 nad;
    {
        const float* a = actb;
        nB0 = *(const float4*)(a + DI + n0);
        nB1 = *(const float4*)(a + DI + n0 + 4);
        nC0 = *(const float4*)(a + DI + DSTATE + n0);
        nC1 = *(const float4*)(a + DI + DSTATE + n0 + 4);
        nxv = a[h * HD + p];
        nad = dtA[h];
    }

    for (int t = 0; t < Lseq; t++) {
        float4 B0 = nB0, B1 = nB1, C0 = nC0, C1 = nC1;
        float xv = nxv;
        float2 ad = nad;

        if (t + 1 < Lseq) {
            const float* a = actb + (size_t)(t + 1) * CONVD;
            nB0 = *(const float4*)(a + DI + n0);
            nB1 = *(const float4*)(a + DI + n0 + 4);
            nC0 = *(const float4*)(a + DI + DSTATE + n0);
            nC1 = *(const float4*)(a + DI + DSTATE + n0 + 4);
            nxv = a[h * HD + p];
            nad = dtA[(size_t)(t + 1) * NH + h];
        }

        float dA = ad.x;
        float dtx = ad.y * xv;

        float y = 0.f;
        S[0] = S[0] * dA + dtx * B0.x; y += S[0] * C0.x;
        S[1] = S[1] * dA + dtx * B0.y; y += S[1] * C0.y;
        S[2] = S[2] * dA + dtx * B0.z; y += S[2] * C0.z;
        S[3] = S[3] * dA + dtx * B0.w; y += S[3] * C0.w;
        S[4] = S[4] * dA + dtx * B1.x; y += S[4] * C1.x;
        S[5] = S[5] * dA + dtx * B1.y; y += S[5] * C1.y;
        S[6] = S[6] * dA + dtx * B1.z; y += S[6] * C1.z;
        S[7] = S[7] * dA + dtx * B1.w; y += S[7] * C1.w;

        y += __shfl_xor_sync(0xFFFFFFFFu, y, 1);
        y += __shfl_xor_sync(0xFFFFFFFFu, y, 2);
        y += __shfl_xor_sync(0xFFFFFFFFu, y, 4);

        if (writer) {
            int pl = d ? (Lseq - 1 - t) : t;
            yb[(size_t)pl * DI + h * HD + p] = y + Dh * xv;
        }
    }
}

// ======================= gate + RMSNorm (+tf32 round of y) =======================
__global__ __launch_bounds__(256)
void gate_norm_kernel(const float* __restrict__ norm_w)
{
    const int idx = blockIdx.x;
    const int l = idx & (Lseq - 1);
    const int b = (idx >> 11) & 3;
    const int d = idx >> 13;

    float* yrow = g_y + ((size_t)(d * Bsz + b) * Lseq + l) * DI;
    const float* zrow = g_zxbcdt + ((size_t)b * Lseq + l) * DIP;

    float vals[8];
    float ss = 0.f;
#pragma unroll
    for (int i = 0; i < 8; i++) {
        int c = threadIdx.x + i * 256;
        float yv = yrow[c];
        float z = zrow[c];
        float g = yv * (z / (1.f + expf(-z)));
        vals[i] = g;
        ss += g * g;
    }

    __shared__ float red[8];
#pragma unroll
    for (int m = 16; m > 0; m >>= 1) ss += __shfl_xor_sync(0xFFFFFFFFu, ss, m);
    if ((threadIdx.x & 31) == 0) red[threadIdx.x >> 5] = ss;
    __syncthreads();
    if (threadIdx.x < 8) {
        float v = red[threadIdx.x];
#pragma unroll
        for (int m = 4; m > 0; m >>= 1) v += __shfl_xor_sync(0xFFu, v, m);
        if (threadIdx.x == 0) red[0] = v;
    }
    __syncthreads();
    float scale = rsqrtf(red[0] * (1.f / DI) + 1e-5f);

#pragma unroll
    for (int i = 0; i < 8; i++) {
        int c = threadIdx.x + i * 256;
        yrow[c] = roundtf(vals[i] * scale * norm_w[c]);
    }
}

// ======================= launch =======================
extern "C" void kernel_launch(void* const* d_in, const int* in_sizes, int n_in,
                              void* d_out, int out_size)
{
    const float* x          = (const float*)d_in[0];
    const float* in_proj_w  = (const float*)d_in[1];
    const float* conv_w     = (const float*)d_in[2];
    const float* conv_b     = (const float*)d_in[3];
    const float* dt_bias    = (const float*)d_in[4];
    const float* A_log      = (const float*)d_in[5];
    const float* Dvec       = (const float*)d_in[6];
    const float* norm_w     = (const float*)d_in[7];
    const float* out_proj_w = (const float*)d_in[8];
    const float* proj_w     = (const float*)d_in[9];
    const float* proj_b     = (const float*)d_in[10];
    float* out = (float*)d_out;

    float* zp;  cudaGetSymbolAddress((void**)&zp, g_zxbcdt);
    float* yp;  cudaGetSymbolAddress((void**)&yp, g_y);
    float* cp;  cudaGetSymbolAddress((void**)&cp, g_cat);
    float* xr;  cudaGetSymbolAddress((void**)&xr, g_xr);
    float* wT;  cudaGetSymbolAddress((void**)&wT, g_wT);

    float* inT   = wT;                          // [4256,1024]
    float* outT  = wT + 4256 * 1024;            // [1024,2048]
    float* projT = outT + 1024 * 2048;          // [1024,2048]

    cudaFuncSetAttribute(gemm_wmma<1024, false, false>, cudaFuncAttributeMaxDynamicSharedMemorySize, GEMM_SMEM);
    cudaFuncSetAttribute(gemm_wmma<2048, true,  true >, cudaFuncAttributeMaxDynamicSharedMemorySize, GEMM_SMEM);
    cudaFuncSetAttribute(gemm_wmma<2048, false, false>, cudaFuncAttributeMaxDynamicSharedMemorySize, GEMM_SMEM);

    dim3 tb(32, 8);
    // launch order chosen so the profiler's capture slot lands on the in_proj GEMM
    round_kernel<<<(NTOK * DM) / 1024, 256>>>(x, xr);
    transpose_kernel<<<dim3(DIP / 32, DM / 32), tb>>>(in_proj_w, inT, DM, DIP);
    transpose2_kernel<<<dim3(DM / 32, DI / 32, 2), tb>>>(out_proj_w, outT, proj_w, projT);

    // 1) in_proj: zxbcdt[8192,4256] = xr @ inT^T
    gemm_wmma<1024, false, false><<<dim3((DIP + TNn - 1) / TNn, NTOK / TMm), 256, GEMM_SMEM>>>(
        xr, inT, zp, DIP, DIP);

    // 2) conv + silu + dt prep (8 timesteps per CTA)
    conv_silu_kernel<<<2 * Bsz * (Lseq / 8), 256>>>(conv_w, conv_b, dt_bias, A_log);

    // 3) selective scan
    scan_kernel<<<2 * Bsz * NH, 512>>>(Dvec);

    // 4) gate + RMSNorm (writes tf32-rounded y)
    gate_norm_kernel<<<2 * NTOK, 256>>>(norm_w);

    // 5) out_proj, both directions in ONE launch (M = 2*NTOK rows of g_y)
    gemm_wmma<2048, true, true><<<dim3(DM / TNn, 2 * NTOK / TMm), 256, GEMM_SMEM>>>(
        yp, outT, cp, DM, 2 * DM);

    // 6) final projection, then bias add
    gemm_wmma<2048, false, false><<<dim3(DM / TNn, NTOK / TMm), 256, GEMM_SMEM>>>(
        cp, projT, out, DM, DM);
    bias_add_kernel<<<NTOK, 256>>>(out, proj_b);
}

// round 13
// speedup vs baseline: 1.1274x; 1.0630x over previous
#include <cuda_runtime.h>
#include <cuda_bf16.h>
#include <mma.h>
#include <cstdint>
#include <math.h>

using namespace nvcuda;

// ---------------- problem constants ----------------
#define Bsz 4
#define Lseq 2048
#define DM 1024
#define DSTATE 64
#define DI 2048          // D_INNER
#define NH 32            // NHEADS
#define HD 64            // HEADDIM
#define CONVD 2176       // CONV_DIM
#define DIP 4256         // D_IN_PROJ
#define NTOK (Bsz*Lseq)  // 8192

// ---------------- scratch (static device memory; no allocations) ----------------
__device__ float g_zxbcdt[(size_t)NTOK * DIP];
__device__ float g_act[2ull * NTOK * CONVD];
__device__ float2 g_dtA[2ull * NTOK * NH];
__device__ float g_y[2ull * NTOK * DI];
__device__ float g_ws[8ull * 1024 * 1024];     // WcT[1024*4096] + opr[2048*1024]
__device__ float g_xr[(size_t)NTOK * DM];      // tf32-rounded x
// transposed+rounded weights: inT[4256,1024], projT[1024,2048]
__device__ float g_wT[4256*1024 + 1024*2048];

// ======================= small helpers =======================
__device__ __forceinline__ uint32_t smem_u32(const void* p) {
    uint32_t a;
    asm("{ .reg .u64 t; cvta.to.shared.u64 t, %1; cvt.u32.u64 %0, t; }" : "=r"(a) : "l"(p));
    return a;
}
__device__ __forceinline__ void cp16(uint32_t dst, const float* src, bool v) {
    asm volatile("cp.async.cg.shared.global [%0], [%1], 16, %2;"
                 :: "r"(dst), "l"(src), "r"(v ? 16u : 0u));
}
#define CP_COMMIT() asm volatile("cp.async.commit_group;" ::: "memory")
#define CP_WAIT1()  asm volatile("cp.async.wait_group 1;" ::: "memory")
#define CP_WAIT0()  asm volatile("cp.async.wait_group 0;" ::: "memory")

__device__ __forceinline__ float roundtf(float v) {
    uint32_t u;
    asm("cvt.rna.tf32.f32 %0, %1;" : "=r"(u) : "f"(v));
    return __uint_as_float(u);
}

// ======================= TF32 WMMA GEMM (inputs pre-rounded to tf32) =======================
// C[M, Nvalid] = [A | A2][M, K] @ Bt[Nvalid, K]^T.  A row-major (lda), Bt row-major (ldb).
// Chunks kn < KSPLIT read A at col kn*32; chunks >= KSPLIT read A2 at col (kn-KSPLIT)*32.
// CTA tile 128(M) x 256(N), 8 warps (2M x 4N), warp tile 64x64.
// K-chunk 32, 3-stage cp.async ring, ONE __syncthreads per chunk, 1 CTA/SM.
#define TMm 128
#define TNn 256
#define PAD 36
#define A_FLOATS (TMm * PAD)                  // 4608
#define B_FLOATS (TNn * PAD)                  // 9216
#define STAGE_FLOATS (A_FLOATS + B_FLOATS)    // 13824
#define GEMM_SMEM (3 * STAGE_FLOATS * 4)      // 165888 B

template<int K, bool ROUND, int KSPLIT>
__global__ __launch_bounds__(256)
void gemm_wmma(const float* __restrict__ A, const float* __restrict__ A2, int lda,
               const float* __restrict__ Bt, int ldb,
               float* __restrict__ C, int Nvalid, int ldc)
{
    extern __shared__ float sm[];

    const int tid = threadIdx.x;
    const int wid = tid >> 5;
    const int bm = blockIdx.y * TMm;
    const int bn = blockIdx.x * TNn;

    const int wm = (wid & 1) * 64;       // 2 warps in M
    const int wn = (wid >> 1) * 64;      // 4 warps in N

    // loader mapping: rows tr + i*32, 16B chunk c4 within 128B (32-float) row
    const int tr = tid >> 3;
    const int c4 = tid & 7;
    const uint32_t smb = smem_u32(sm);
    const float* pA  = A  + (size_t)(bm + tr) * lda + c4 * 4;
    const float* pA2 = A2 + (size_t)(bm + tr) * lda + c4 * 4;
    const float* pB  = Bt + (size_t)(bn + tr) * ldb + c4 * 4;
    bool bok[8];
#pragma unroll
    for (int i = 0; i < 8; i++) bok[i] = (bn + tr + i * 32) < Nvalid;

    constexpr int NC = K / 32;

    auto load_chunk = [&](int kn) {
        uint32_t base = smb + (uint32_t)((kn % 3) * STAGE_FLOATS) * 4;
        uint32_t ab = base + (tr * PAD + c4 * 4) * 4;
        uint32_t bb = base + (uint32_t)A_FLOATS * 4 + (tr * PAD + c4 * 4) * 4;
        const float* a = (KSPLIT < NC && kn >= KSPLIT)
                         ? pA2 + (size_t)(kn - KSPLIT) * 32
                         : pA + (size_t)kn * 32;
        const float* b = pB + (size_t)kn * 32;
#pragma unroll
        for (int i = 0; i < 4; i++)
            cp16(ab + i * (32 * PAD * 4), a + (size_t)i * 32 * lda, true);
#pragma unroll
        for (int i = 0; i < 8; i++)
            cp16(bb + i * (32 * PAD * 4), b + (size_t)i * 32 * ldb, bok[i]);
        CP_COMMIT();
    };

    wmma::fragment<wmma::accumulator, 16, 16, 8, float> acc[4][4];
#pragma unroll
    for (int mt = 0; mt < 4; mt++)
#pragma unroll
        for (int nt = 0; nt < 4; nt++) wmma::fill_fragment(acc[mt][nt], 0.f);

    load_chunk(0);
    load_chunk(1);

    for (int kc = 0; kc < NC; kc++) {
        if (kc == NC - 1) { CP_WAIT0(); } else { CP_WAIT1(); }
        __syncthreads();                     // single barrier per chunk
        if (kc + 2 < NC) load_chunk(kc + 2); // stage (kc+2)%3 last read at kc-1

        const float* as = sm + (kc % 3) * STAGE_FLOATS;
        const float* bs = as + A_FLOATS;

#pragma unroll
        for (int k8 = 0; k8 < 4; k8++) {
            const int k0 = k8 * 8;
            wmma::fragment<wmma::matrix_a, 16, 16, 8, wmma::precision::tf32, wmma::row_major> af[4];
            wmma::fragment<wmma::matrix_b, 16, 16, 8, wmma::precision::tf32, wmma::col_major> bf[4];
#pragma unroll
            for (int mt = 0; mt < 4; mt++)
                wmma::load_matrix_sync(af[mt], as + (wm + mt * 16) * PAD + k0, PAD);
#pragma unroll
            for (int nt = 0; nt < 4; nt++)
                wmma::load_matrix_sync(bf[nt], bs + (wn + nt * 16) * PAD + k0, PAD);
#pragma unroll
            for (int mt = 0; mt < 4; mt++)
#pragma unroll
                for (int nt = 0; nt < 4; nt++)
                    wmma::mma_sync(acc[mt][nt], af[mt], bf[nt], acc[mt][nt]);
        }
    }

    // epilogue (N remainders are multiples of 16 for our shapes)
#pragma unroll
    for (int mt = 0; mt < 4; mt++) {
#pragma unroll
        for (int nt = 0; nt < 4; nt++) {
            int row0 = bm + wm + mt * 16;
            int col0 = bn + wn + nt * 16;
            if (col0 + 16 <= Nvalid) {
                if (ROUND) {
#pragma unroll
                    for (int e = 0; e < acc[mt][nt].num_elements; e++)
                        acc[mt][nt].x[e] = roundtf(acc[mt][nt].x[e]);
                }
                wmma::store_matrix_sync(C + (size_t)row0 * ldc + col0, acc[mt][nt],
                                        ldc, wmma::mem_row_major);
            }
        }
    }
}

// ======================= bias add (final projection) =======================
__global__ __launch_bounds__(256)
void bias_add_kernel(float* __restrict__ C, const float* __restrict__ bias)
{
    int row = blockIdx.x;
    int c = threadIdx.x * 4;
    float4 v = *(float4*)(C + (size_t)row * DM + c);
    float4 b = *(const float4*)(bias + c);
    v.x += b.x; v.y += b.y; v.z += b.z; v.w += b.w;
    *(float4*)(C + (size_t)row * DM + c) = v;
}

// ======================= round to tf32 (elementwise) =======================
__global__ __launch_bounds__(256)
void round_kernel(const float* __restrict__ in, float* __restrict__ out)
{
    size_t i = ((size_t)blockIdx.x * 256 + threadIdx.x) * 4;
    float4 v = *(const float4*)(in + i);
    v.x = roundtf(v.x); v.y = roundtf(v.y); v.z = roundtf(v.z); v.w = roundtf(v.w);
    *(float4*)(out + i) = v;
}

// ======================= weight transpose (+tf32 round) =======================
__global__ __launch_bounds__(256)
void transpose_kernel(const float* __restrict__ B, float* __restrict__ Bt, int K, int N)
{
    __shared__ float t[32][33];
    int tx = threadIdx.x, ty = threadIdx.y;
    int n0 = blockIdx.x * 32, k0 = blockIdx.y * 32;
#pragma unroll
    for (int r = 0; r < 4; r++)
        t[ty + r * 8][tx] = B[(size_t)(k0 + ty + r * 8) * N + n0 + tx];
    __syncthreads();
#pragma unroll
    for (int r = 0; r < 4; r++)
        Bt[(size_t)(n0 + ty + r * 8) * K + k0 + tx] = roundtf(t[tx][ty + r * 8]);
}

// ======================= conv + silu + dt softplus/dA (8 timesteps per CTA) =======================
__global__ __launch_bounds__(256)
void conv_silu_kernel(const float* __restrict__ conv_w, const float* __restrict__ conv_b,
                      const float* __restrict__ dt_bias, const float* __restrict__ A_log)
{
    const int seg = blockIdx.x;
    const int t0 = (seg & (Lseq / 8 - 1)) * 8;
    const int b = (seg >> 8) & 3;
    const int d = seg >> 10;

    float* outbase = g_act + ((size_t)(d * Bsz + b) * Lseq + t0) * CONVD;

    for (int c = threadIdx.x; c < CONVD; c += 256) {
        float w0 = conv_w[c * 4 + 0], w1 = conv_w[c * 4 + 1];
        float w2 = conv_w[c * 4 + 2], w3 = conv_w[c * 4 + 3];
        float cb = conv_b[c];
        float taps[11];
#pragma unroll
        for (int j = 0; j < 11; j++) {
            int lt = t0 - 3 + j;
            if (lt < 0) { taps[j] = 0.f; }
            else {
                int pl = d ? (Lseq - 1 - lt) : lt;
                taps[j] = g_zxbcdt[((size_t)b * Lseq + pl) * DIP + DI + c];
            }
        }
#pragma unroll
        for (int k = 0; k < 8; k++) {
            float acc = cb + taps[k] * w0 + taps[k + 1] * w1
                           + taps[k + 2] * w2 + taps[k + 3] * w3;
            outbase[(size_t)k * CONVD + c] = acc / (1.f + expf(-acc));
        }
    }

    {
        int k = threadIdx.x >> 5;
        int h = threadIdx.x & 31;
        int t = t0 + k;
        int pl = d ? (Lseq - 1 - t) : t;
        float raw = g_zxbcdt[((size_t)b * Lseq + pl) * DIP + (DIP - NH) + h] + dt_bias[h];
        float dt = (raw > 20.f) ? raw : log1pf(expf(raw));
        float A = -expf(A_log[h]);
        float dA = expf(dt * A);
        g_dtA[((size_t)(d * Bsz + b) * Lseq + t) * NH + h] = make_float2(dA, dt);
    }
}

// ======================= sequential selective scan (with prefetch) =======================
__global__ __launch_bounds__(512)
void scan_kernel(const float* __restrict__ Dvec)
{
    const int h = blockIdx.x & 31;
    const int b = (blockIdx.x >> 5) & 3;
    const int d = blockIdx.x >> 7;

    const int lane = threadIdx.x & 31;
    const int w = threadIdx.x >> 5;
    const int p = w * 4 + (lane >> 3);
    const int n0 = (lane & 7) * 8;

    const float* actb = g_act + (size_t)(d * Bsz + b) * Lseq * CONVD;
    const float2* dtA = g_dtA + (size_t)(d * Bsz + b) * Lseq * NH;
    float* yb = g_y + (size_t)(d * Bsz + b) * Lseq * DI;

    const float Dh = Dvec[h];
    const bool writer = ((lane & 7) == 0);

    float S[8];
#pragma unroll
    for (int j = 0; j < 8; j++) S[j] = 0.f;

    float4 nB0, nB1, nC0, nC1;
    float nxv;
    float2 nad;
    {
        const float* a = actb;
        nB0 = *(const float4*)(a + DI + n0);
        nB1 = *(const float4*)(a + DI + n0 + 4);
        nC0 = *(const float4*)(a + DI + DSTATE + n0);
        nC1 = *(const float4*)(a + DI + DSTATE + n0 + 4);
        nxv = a[h * HD + p];
        nad = dtA[h];
    }

    for (int t = 0; t < Lseq; t++) {
        float4 B0 = nB0, B1 = nB1, C0 = nC0, C1 = nC1;
        float xv = nxv;
        float2 ad = nad;

        if (t + 1 < Lseq) {
            const float* a = actb + (size_t)(t + 1) * CONVD;
            nB0 = *(const float4*)(a + DI + n0);
            nB1 = *(const float4*)(a + DI + n0 + 4);
            nC0 = *(const float4*)(a + DI + DSTATE + n0);
            nC1 = *(const float4*)(a + DI + DSTATE + n0 + 4);
            nxv = a[h * HD + p];
            nad = dtA[(size_t)(t + 1) * NH + h];
        }

        float dA = ad.x;
        float dtx = ad.y * xv;

        float y = 0.f;
        S[0] = S[0] * dA + dtx * B0.x; y += S[0] * C0.x;
        S[1] = S[1] * dA + dtx * B0.y; y += S[1] * C0.y;
        S[2] = S[2] * dA + dtx * B0.z; y += S[2] * C0.z;
        S[3] = S[3] * dA + dtx * B0.w; y += S[3] * C0.w;
        S[4] = S[4] * dA + dtx * B1.x; y += S[4] * C1.x;
        S[5] = S[5] * dA + dtx * B1.y; y += S[5] * C1.y;
        S[6] = S[6] * dA + dtx * B1.z; y += S[6] * C1.z;
        S[7] = S[7] * dA + dtx * B1.w; y += S[7] * C1.w;

        y += __shfl_xor_sync(0xFFFFFFFFu, y, 1);
        y += __shfl_xor_sync(0xFFFFFFFFu, y, 2);
        y += __shfl_xor_sync(0xFFFFFFFFu, y, 4);

        if (writer) {
            int pl = d ? (Lseq - 1 - t) : t;
            yb[(size_t)pl * DI + h * HD + p] = y + Dh * xv;
        }
    }
}

// ======================= gate + RMSNorm (+tf32 round of y) =======================
__global__ __launch_bounds__(256)
void gate_norm_kernel(const float* __restrict__ norm_w)
{
    const int idx = blockIdx.x;
    const int l = idx & (Lseq - 1);
    const int b = (idx >> 11) & 3;
    const int d = idx >> 13;

    float* yrow = g_y + ((size_t)(d * Bsz + b) * Lseq + l) * DI;
    const float* zrow = g_zxbcdt + ((size_t)b * Lseq + l) * DIP;

    float vals[8];
    float ss = 0.f;
#pragma unroll
    for (int i = 0; i < 8; i++) {
        int c = threadIdx.x + i * 256;
        float yv = yrow[c];
        float z = zrow[c];
        float g = yv * (z / (1.f + expf(-z)));
        vals[i] = g;
        ss += g * g;
    }

    __shared__ float red[8];
#pragma unroll
    for (int m = 16; m > 0; m >>= 1) ss += __shfl_xor_sync(0xFFFFFFFFu, ss, m);
    if ((threadIdx.x & 31) == 0) red[threadIdx.x >> 5] = ss;
    __syncthreads();
    if (threadIdx.x < 8) {
        float v = red[threadIdx.x];
#pragma unroll
        for (int m = 4; m > 0; m >>= 1) v += __shfl_xor_sync(0xFFu, v, m);
        if (threadIdx.x == 0) red[0] = v;
    }
    __syncthreads();
    float scale = rsqrtf(red[0] * (1.f / DI) + 1e-5f);

#pragma unroll
    for (int i = 0; i < 8; i++) {
        int c = threadIdx.x + i * 256;
        yrow[c] = roundtf(vals[i] * scale * norm_w[c]);
    }
}

// ======================= launch =======================
extern "C" void kernel_launch(void* const* d_in, const int* in_sizes, int n_in,
                              void* d_out, int out_size)
{
    const float* x          = (const float*)d_in[0];
    const float* in_proj_w  = (const float*)d_in[1];
    const float* conv_w     = (const float*)d_in[2];
    const float* conv_b     = (const float*)d_in[3];
    const float* dt_bias    = (const float*)d_in[4];
    const float* A_log      = (const float*)d_in[5];
    const float* Dvec       = (const float*)d_in[6];
    const float* norm_w     = (const float*)d_in[7];
    const float* out_proj_w = (const float*)d_in[8];
    const float* proj_w     = (const float*)d_in[9];
    const float* proj_b     = (const float*)d_in[10];
    float* out = (float*)d_out;

    float* zp;  cudaGetSymbolAddress((void**)&zp, g_zxbcdt);
    float* yp;  cudaGetSymbolAddress((void**)&yp, g_y);
    float* ws;  cudaGetSymbolAddress((void**)&ws, g_ws);
    float* xr;  cudaGetSymbolAddress((void**)&xr, g_xr);
    float* wT;  cudaGetSymbolAddress((void**)&wT, g_wT);

    float* inT   = wT;                          // [4256,1024]
    float* projT = wT + 4256 * 1024;            // [1024,2048] = proj_w^T, rounded
    float* WcT   = ws;                          // [1024,4096] fused output weight^T
    float* opr   = ws + 1024 * 4096;            // [2048,1024] rounded out_proj_w

    cudaFuncSetAttribute(gemm_wmma<1024, false, 1 << 20>, cudaFuncAttributeMaxDynamicSharedMemorySize, GEMM_SMEM);
    cudaFuncSetAttribute(gemm_wmma<1024, true,  1 << 20>, cudaFuncAttributeMaxDynamicSharedMemorySize, GEMM_SMEM);
    cudaFuncSetAttribute(gemm_wmma<4096, false, 64>,      cudaFuncAttributeMaxDynamicSharedMemorySize, GEMM_SMEM);

    dim3 tb(32, 8);
    // (1) round x    (2) transpose in_proj    (3) round out_proj_w    (4) transpose proj_w
    round_kernel<<<(NTOK * DM) / 1024, 256>>>(x, xr);
    transpose_kernel<<<dim3(DIP / 32, DM / 32), tb>>>(in_proj_w, inT, DM, DIP);
    round_kernel<<<(DI * DM) / 1024, 256>>>(out_proj_w, opr);
    transpose_kernel<<<dim3(DM / 32, (2 * DM) / 32), tb>>>(proj_w, projT, 2 * DM, DM);

    // (5) W1T = projT[:, :1024] @ opr^T  -> WcT cols [0,2048)
    gemm_wmma<1024, true, 1 << 20><<<dim3(DI / TNn, DM / TMm), 256, GEMM_SMEM>>>(
        projT, projT, 2 * DM, opr, DM, WcT, DI, 2 * DI);

    // (6) in_proj: zxbcdt[8192,4256] = xr @ inT^T   <-- profiler capture slot
    gemm_wmma<1024, false, 1 << 20><<<dim3((DIP + TNn - 1) / TNn, NTOK / TMm), 256, GEMM_SMEM>>>(
        xr, xr, DM, inT, DM, zp, DIP, DIP);

    // (7) W2T = projT[:, 1024:] @ opr^T -> WcT cols [2048,4096)
    gemm_wmma<1024, true, 1 << 20><<<dim3(DI / TNn, DM / TMm), 256, GEMM_SMEM>>>(
        projT + DM, projT + DM, 2 * DM, opr, DM, WcT + DI, DI, 2 * DI);

    // (8) conv + silu + dt prep (8 timesteps per CTA)
    conv_silu_kernel<<<2 * Bsz * (Lseq / 8), 256>>>(conv_w, conv_b, dt_bias, A_log);

    // (9) selective scan
    scan_kernel<<<2 * Bsz * NH, 512>>>(Dvec);

    // (10) gate + RMSNorm (writes tf32-rounded y)
    gate_norm_kernel<<<2 * NTOK, 256>>>(norm_w);

    // (11) fused output: out = [y_fwd | y_bwd] @ WcT^T   (K = 4096, A-switch at chunk 64)
    gemm_wmma<4096, false, 64><<<dim3(DM / TNn, NTOK / TMm), 256, GEMM_SMEM>>>(
        yp, yp + (size_t)NTOK * DI, DI, WcT, 2 * DI, out, DM, DM);

    // (12) bias add
    bias_add_kernel<<<NTOK, 256>>>(out, proj_b);
}